// round 1
// baseline (speedup 1.0000x reference)
#include <cuda_runtime.h>

// Problem constants (from reference)
#define S_TOK 131072
#define DIM   512
#define VOCAB 100000

// Scratch: per-vocab counts. Sums accumulate directly into d_out (it is
// preallocated to V*D floats and we fully overwrite it in finalize).
__device__ int g_counts[VOCAB];

// ---------------------------------------------------------------------------
// Kernel 1: zero the counts array
// ---------------------------------------------------------------------------
__global__ void zero_counts_kernel() {
    int i = blockIdx.x * blockDim.x + threadIdx.x;
    if (i < VOCAB) g_counts[i] = 0;
}

// ---------------------------------------------------------------------------
// Kernel 2: zero d_out (used as the segment-sum scratch)
// ---------------------------------------------------------------------------
__global__ void zero_sums_kernel(float4* __restrict__ sums4) {
    long i = (long)blockIdx.x * blockDim.x + threadIdx.x;
    long n4 = (long)VOCAB * (DIM / 4);
    long stride = (long)gridDim.x * blockDim.x;
    float4 z = make_float4(0.f, 0.f, 0.f, 0.f);
    for (; i < n4; i += stride) sums4[i] = z;
}

// ---------------------------------------------------------------------------
// Kernel 3: scatter. One warp per token. If masked, atomically add the
// token's 512-float row of `out` into sums[v], and bump counts[v].
// ---------------------------------------------------------------------------
__global__ void scatter_kernel(const float4* __restrict__ out4,
                               const int* __restrict__ l2_data,
                               const int* __restrict__ l2_idxs,
                               float* __restrict__ sums) {
    int gwarp = (blockIdx.x * blockDim.x + threadIdx.x) >> 5;
    int lane  = threadIdx.x & 31;
    if (gwarp >= S_TOK) return;

    if (l2_idxs[gwarp] != 1) return;
    int v = l2_data[gwarp];

    if (lane == 0) atomicAdd(&g_counts[v], 1);

    const float4* src = out4 + (long)gwarp * (DIM / 4);
    float*        dst = sums + (long)v * DIM;

#pragma unroll
    for (int i = 0; i < 4; i++) {
        int c = lane + i * 32;          // float4 index within the row (0..127)
        float4 x = src[c];
        atomicAdd(dst + c * 4 + 0, x.x);
        atomicAdd(dst + c * 4 + 1, x.y);
        atomicAdd(dst + c * 4 + 2, x.z);
        atomicAdd(dst + c * 4 + 3, x.w);
    }
}

// ---------------------------------------------------------------------------
// Kernel 4: finalize. new_w = count>0 ? 0.5*w + 0.5*sum/count : w
// Vectorized float4 over V*D. Reads sums in-place from d_out, overwrites.
// ---------------------------------------------------------------------------
__global__ void finalize_kernel(const float4* __restrict__ w4,
                                float4* __restrict__ out4) {
    long i = (long)blockIdx.x * blockDim.x + threadIdx.x;
    long n4 = (long)VOCAB * (DIM / 4);
    if (i >= n4) return;

    int row = (int)(i >> 7);            // i / (DIM/4=128)
    int c = g_counts[row];
    float4 wv = w4[i];
    float4 o;
    if (c > 0) {
        float4 s = out4[i];
        float inv = 0.5f / (float)c;
        o.x = 0.5f * wv.x + s.x * inv;
        o.y = 0.5f * wv.y + s.y * inv;
        o.z = 0.5f * wv.z + s.z * inv;
        o.w = 0.5f * wv.w + s.w * inv;
    } else {
        o = wv;
    }
    out4[i] = o;
}

// ---------------------------------------------------------------------------
extern "C" void kernel_launch(void* const* d_in, const int* in_sizes, int n_in,
                              void* d_out, int out_size) {
    const float* out_act   = (const float*)d_in[0];   // [S, D] f32
    const float* l2_weight = (const float*)d_in[1];   // [V, D] f32
    const int*   l2_data   = (const int*)d_in[2];     // [S] i32
    const int*   l2_idxs   = (const int*)d_in[3];     // [S] i32
    float* outp = (float*)d_out;                      // [V, D] f32

    (void)in_sizes; (void)n_in; (void)out_size;

    // 1. zero counts
    zero_counts_kernel<<<(VOCAB + 255) / 256, 256>>>();

    // 2. zero sums (d_out)
    {
        long n4 = (long)VOCAB * (DIM / 4);
        int threads = 256;
        int blocks = (int)((n4 + threads - 1) / threads);
        if (blocks > 65535 * 8) blocks = 65535 * 8;
        zero_sums_kernel<<<blocks, threads>>>((float4*)outp);
    }

    // 3. scatter: one warp per token -> S/8 blocks of 256 threads
    {
        int warps_per_block = 256 / 32;
        int blocks = S_TOK / warps_per_block;
        scatter_kernel<<<blocks, 256>>>((const float4*)out_act, l2_data,
                                        l2_idxs, outp);
    }

    // 4. finalize
    {
        long n4 = (long)VOCAB * (DIM / 4);
        int threads = 256;
        int blocks = (int)((n4 + threads - 1) / threads);
        finalize_kernel<<<blocks, threads>>>((const float4*)l2_weight,
                                             (float4*)outp);
    }
}

// round 2
// speedup vs baseline: 1.1585x; 1.1585x over previous
#include <cuda_runtime.h>

// Problem constants (from reference)
#define S_TOK 131072
#define DIM   512
#define VOCAB 100000

// Scratch (device globals — no runtime allocation allowed).
__device__ int g_counts[VOCAB];   // tokens per vocab row
__device__ int g_n;               // number of masked tokens (compacted)
__device__ int g_tok[S_TOK];      // compacted token index
__device__ int g_vid[S_TOK];      // compacted vocab id

// ---------------------------------------------------------------------------
// Kernel 0: zero counts + n
// ---------------------------------------------------------------------------
__global__ void zero_counts_kernel() {
    int i = blockIdx.x * blockDim.x + threadIdx.x;
    if (i < VOCAB) g_counts[i] = 0;
    if (i == 0) g_n = 0;
}

// ---------------------------------------------------------------------------
// Kernel 1: compact masked tokens + histogram counts
// ---------------------------------------------------------------------------
__global__ void compact_kernel(const int* __restrict__ l2_data,
                               const int* __restrict__ l2_idxs) {
    int i = blockIdx.x * blockDim.x + threadIdx.x;
    if (i >= S_TOK) return;
    if (l2_idxs[i] == 1) {
        int v = l2_data[i];
        int pos = atomicAdd(&g_n, 1);
        g_tok[pos] = i;
        g_vid[pos] = v;
        atomicAdd(&g_counts[v], 1);
    }
}

// ---------------------------------------------------------------------------
// Kernel 2: zero ONLY rows that will be accumulated with atomics (count >= 2).
// Rows with count == 1 are written by a plain store in the scatter; rows with
// count == 0 are fully overwritten by finalize.
// ---------------------------------------------------------------------------
__global__ void zero_multi_rows_kernel(float4* __restrict__ sums4) {
    int row = blockIdx.x;
    if (g_counts[row] < 2) return;
    float4 z = make_float4(0.f, 0.f, 0.f, 0.f);
    sums4[(long)row * (DIM / 4) + threadIdx.x] = z;   // 128 threads = 1 row
}

// ---------------------------------------------------------------------------
// Kernel 3: scatter over the compacted token list. One warp per token.
//  count==1  -> plain 16B stores (no zero, no atomic)
//  count>=2  -> red.global.add.v4.f32 (16B vector reduction, sm_90+)
// ---------------------------------------------------------------------------
__global__ void scatter_kernel(const float4* __restrict__ out4,
                               float* __restrict__ sums) {
    int gwarp = (blockIdx.x * blockDim.x + threadIdx.x) >> 5;
    int lane  = threadIdx.x & 31;
    if (gwarp >= g_n) return;

    int tok = g_tok[gwarp];
    int v   = g_vid[gwarp];
    bool single = (g_counts[v] == 1);

    const float4* src = out4 + (long)tok * (DIM / 4);
    float4*       dst = (float4*)(sums + (long)v * DIM);

#pragma unroll
    for (int i = 0; i < 4; i++) {
        int c = lane + i * 32;          // float4 index within the row (0..127)
        float4 x = src[c];
        if (single) {
            dst[c] = x;
        } else {
            asm volatile(
                "red.global.add.v4.f32 [%0], {%1, %2, %3, %4};"
                :: "l"(dst + c), "f"(x.x), "f"(x.y), "f"(x.z), "f"(x.w)
                : "memory");
        }
    }
}

// ---------------------------------------------------------------------------
// Kernel 4: finalize. new_w = count>0 ? 0.5*w + 0.5*sum/count : w
// ---------------------------------------------------------------------------
__global__ void finalize_kernel(const float4* __restrict__ w4,
                                float4* __restrict__ out4) {
    long i = (long)blockIdx.x * blockDim.x + threadIdx.x;
    long n4 = (long)VOCAB * (DIM / 4);
    if (i >= n4) return;

    int row = (int)(i >> 7);            // i / 128
    int c = g_counts[row];
    float4 wv = w4[i];
    float4 o;
    if (c > 0) {
        float4 s = out4[i];
        float inv = 0.5f / (float)c;
        o.x = 0.5f * wv.x + s.x * inv;
        o.y = 0.5f * wv.y + s.y * inv;
        o.z = 0.5f * wv.z + s.z * inv;
        o.w = 0.5f * wv.w + s.w * inv;
    } else {
        o = wv;
    }
    out4[i] = o;
}

// ---------------------------------------------------------------------------
extern "C" void kernel_launch(void* const* d_in, const int* in_sizes, int n_in,
                              void* d_out, int out_size) {
    const float* out_act   = (const float*)d_in[0];   // [S, D] f32
    const float* l2_weight = (const float*)d_in[1];   // [V, D] f32
    const int*   l2_data   = (const int*)d_in[2];     // [S] i32
    const int*   l2_idxs   = (const int*)d_in[3];     // [S] i32
    float* outp = (float*)d_out;                      // [V, D] f32

    (void)in_sizes; (void)n_in; (void)out_size;

    // 0. zero counts + n
    zero_counts_kernel<<<(VOCAB + 255) / 256, 256>>>();

    // 1. compact masked tokens, build counts
    compact_kernel<<<(S_TOK + 255) / 256, 256>>>(l2_data, l2_idxs);

    // 2. zero only multi-token rows (the atomic targets)
    zero_multi_rows_kernel<<<VOCAB, DIM / 4>>>((float4*)outp);

    // 3. scatter (worst case: all S tokens masked). Warp per token.
    {
        int warps_per_block = 256 / 32;
        int blocks = S_TOK / warps_per_block;
        scatter_kernel<<<blocks, 256>>>((const float4*)out_act, outp);
    }

    // 4. finalize
    {
        long n4 = (long)VOCAB * (DIM / 4);
        int threads = 256;
        int blocks = (int)((n4 + threads - 1) / threads);
        finalize_kernel<<<blocks, threads>>>((const float4*)l2_weight,
                                             (float4*)outp);
    }
}

// round 3
// speedup vs baseline: 1.5601x; 1.3466x over previous
#include <cuda_runtime.h>

// Problem constants (from reference)
#define S_TOK 131072
#define DIM   512
#define VOCAB 100000

// Scratch (device globals — no runtime allocation allowed).
__device__ int g_counts[VOCAB];   // tokens per vocab row
__device__ int g_n;               // number of masked tokens (compacted)
__device__ int g_nm;              // number of multi-count (c>=2) rows
__device__ int g_tok[S_TOK];      // compacted token index
__device__ int g_vid[S_TOK];      // compacted vocab id
__device__ int g_multi[VOCAB];    // worklist of rows with c>=2

// ---------------------------------------------------------------------------
// Kernel A: zero counts + counters
// ---------------------------------------------------------------------------
__global__ void zero_counts_kernel() {
    int i = blockIdx.x * blockDim.x + threadIdx.x;
    if (i < VOCAB) g_counts[i] = 0;
    if (i == 0) { g_n = 0; g_nm = 0; }
}

// ---------------------------------------------------------------------------
// Kernel B: compact masked tokens + histogram counts
// ---------------------------------------------------------------------------
__global__ void compact_kernel(const int* __restrict__ l2_data,
                               const int* __restrict__ l2_idxs) {
    int i = blockIdx.x * blockDim.x + threadIdx.x;
    if (i >= S_TOK) return;
    if (l2_idxs[i] == 1) {
        int v = l2_data[i];
        int pos = atomicAdd(&g_n, 1);
        g_tok[pos] = i;
        g_vid[pos] = v;
        atomicAdd(&g_counts[v], 1);
    }
}

// ---------------------------------------------------------------------------
// Kernel C: build worklist of rows needing atomic accumulation (c >= 2)
// ---------------------------------------------------------------------------
__global__ void build_multi_kernel() {
    int i = blockIdx.x * blockDim.x + threadIdx.x;
    if (i >= VOCAB) return;
    if (g_counts[i] >= 2) {
        int pos = atomicAdd(&g_nm, 1);
        g_multi[pos] = i;
    }
}

// ---------------------------------------------------------------------------
// Kernel D: init multi rows with c*w. After scatter adds Sum(x), the row holds
// c*w + Sum(x); finalize scales by 0.5/c -> 0.5*w + 0.5*mean(x).
// Fixed small grid, grid-stride over the worklist (one block per row/iter).
// ---------------------------------------------------------------------------
__global__ void init_multi_kernel(const float4* __restrict__ w4,
                                  float4* __restrict__ sums4) {
    for (int j = blockIdx.x; j < g_nm; j += gridDim.x) {
        int row = g_multi[j];
        float c = (float)g_counts[row];
        long base = (long)row * (DIM / 4);
        float4 wv = w4[base + threadIdx.x];       // 128 threads = 1 row
        float4 o = make_float4(c * wv.x, c * wv.y, c * wv.z, c * wv.w);
        sums4[base + threadIdx.x] = o;
    }
}

// ---------------------------------------------------------------------------
// Kernel E: scatter over the compacted token list. One warp per token,
// grid-stride over tokens.
//  count==1  -> fused EMA: write 0.5*w + 0.5*x final (no atomic, skip finalize)
//  count>=2  -> red.global.add.v4.f32 into the c*w-initialized row
// ---------------------------------------------------------------------------
__global__ void scatter_kernel(const float4* __restrict__ out4,
                               const float4* __restrict__ w4,
                               float* __restrict__ sums) {
    int warp0   = (blockIdx.x * blockDim.x + threadIdx.x) >> 5;
    int nwarps  = (gridDim.x * blockDim.x) >> 5;
    int lane    = threadIdx.x & 31;
    int n       = g_n;

    for (int j = warp0; j < n; j += nwarps) {
        int tok = g_tok[j];
        int v   = g_vid[j];
        bool single = (g_counts[v] == 1);

        const float4* src = out4 + (long)tok * (DIM / 4);
        long vbase = (long)v * (DIM / 4);
        float4* dst = (float4*)sums + vbase;

        if (single) {
#pragma unroll
            for (int i = 0; i < 4; i++) {
                int c = lane + i * 32;
                float4 x  = src[c];
                float4 wv = w4[vbase + c];
                float4 o = make_float4(0.5f * (wv.x + x.x), 0.5f * (wv.y + x.y),
                                       0.5f * (wv.z + x.z), 0.5f * (wv.w + x.w));
                dst[c] = o;
            }
        } else {
#pragma unroll
            for (int i = 0; i < 4; i++) {
                int c = lane + i * 32;
                float4 x = src[c];
                asm volatile(
                    "red.global.add.v4.f32 [%0], {%1, %2, %3, %4};"
                    :: "l"(dst + c), "f"(x.x), "f"(x.y), "f"(x.z), "f"(x.w)
                    : "memory");
            }
        }
    }
}

// ---------------------------------------------------------------------------
// Kernel F: finalize.
//   c==0 -> out = w (copy)
//   c==1 -> already final (written by scatter), skip
//   c>=2 -> out = sums * (0.5/c)       (sums = c*w + Sum(x))
// ---------------------------------------------------------------------------
__global__ void finalize_kernel(const float4* __restrict__ w4,
                                float4* __restrict__ out4) {
    long i = (long)blockIdx.x * blockDim.x + threadIdx.x;
    long n4 = (long)VOCAB * (DIM / 4);
    if (i >= n4) return;

    int row = (int)(i >> 7);            // i / 128
    int c = g_counts[row];
    if (c == 1) return;                 // uniform per-row -> uniform per-warp

    float4 o;
    if (c == 0) {
        o = w4[i];
    } else {
        float4 s = out4[i];
        float inv = 0.5f / (float)c;
        o = make_float4(s.x * inv, s.y * inv, s.z * inv, s.w * inv);
    }
    out4[i] = o;
}

// ---------------------------------------------------------------------------
extern "C" void kernel_launch(void* const* d_in, const int* in_sizes, int n_in,
                              void* d_out, int out_size) {
    const float* out_act   = (const float*)d_in[0];   // [S, D] f32
    const float* l2_weight = (const float*)d_in[1];   // [V, D] f32
    const int*   l2_data   = (const int*)d_in[2];     // [S] i32
    const int*   l2_idxs   = (const int*)d_in[3];     // [S] i32
    float* outp = (float*)d_out;                      // [V, D] f32

    (void)in_sizes; (void)n_in; (void)out_size;

    // A. zero counts + counters
    zero_counts_kernel<<<(VOCAB + 255) / 256, 256>>>();

    // B. compact masked tokens, build counts
    compact_kernel<<<(S_TOK + 255) / 256, 256>>>(l2_data, l2_idxs);

    // C. build multi-row worklist
    build_multi_kernel<<<(VOCAB + 255) / 256, 256>>>();

    // D. init multi rows with c*w (small fixed grid, grid-stride)
    init_multi_kernel<<<2048, DIM / 4>>>((const float4*)l2_weight,
                                         (float4*)outp);

    // E. scatter (grid-stride warps over compacted tokens)
    scatter_kernel<<<2048, 256>>>((const float4*)out_act,
                                  (const float4*)l2_weight, outp);

    // F. finalize
    {
        long n4 = (long)VOCAB * (DIM / 4);
        int threads = 256;
        int blocks = (int)((n4 + threads - 1) / threads);
        finalize_kernel<<<blocks, threads>>>((const float4*)l2_weight,
                                             (float4*)outp);
    }
}